// round 12
// baseline (speedup 1.0000x reference)
#include <cuda_runtime.h>
#include <cuda_bf16.h>
#include <cstdint>
#include <cstddef>

// Problem constants
#define B_   32
#define D_   512
#define P_   1024
#define N_   32768
#define K_   4096
#define TM   128           // rows per CTA
#define TK   32            // codes per k-tile
#define NKT  (K_/TK)       // 128 k-tiles
#define NBLK (N_/TM)       // 256 blocks
#define NTHR 512           // 16 warps: 8 row-groups x 2 col-groups
#define EPS  2.0f          // bf16 score error window (~7 sigma)

#define ASTRIDE 1040       // bytes per staged row (520 bf16): conflict-free ldmatrix

// Dynamic smem layout (bytes)
#define SM_EN    0                       // float[4096] exact ||e_k||^2
#define SM_APP   16384                   // u64[128] packed approx (score,k)
#define SM_EX    17408                   // u64[128] packed exact  (score,k)
#define SM_CNT   18432                   // int[128] in-window candidate count
#define SM_KB    18944                   // int[128] chosen k
#define SM_LRED  19456                   // float[512]
#define SM_A     21504                   // 128 rows * 1040 B = 133120 (1024-aligned)
#define SM_B0    154624                  // 2 buffers * 33280 B
#define SM_BSZ   (TK * ASTRIDE)          // 33280
#define SM_TOTAL 221184

typedef unsigned long long u64;

__device__ float g_enorm[K_];
__device__ float g_losspart[NBLK];
__device__ __nv_bfloat16 g_Ebf[(size_t)K_ * D_];   // E bf16 row-major [k][d]
__device__ __nv_bfloat16 g_Zbf[(size_t)N_ * D_];   // z bf16 row-major [n][d]

// ---------------- PTX helpers (baseline ISA only) ----------------
__device__ __forceinline__ uint32_t smem_u32(const void* p) {
    uint32_t a;
    asm("{ .reg .u64 t; cvta.to.shared.u64 t, %1; cvt.u32.u64 %0, t; }"
        : "=r"(a) : "l"(p));
    return a;
}
__device__ __forceinline__ void cp_async16(uint32_t dst, const void* src) {
    asm volatile("cp.async.cg.shared.global [%0], [%1], 16;"
                 :: "r"(dst), "l"(src) : "memory");
}
__device__ __forceinline__ void cp_commit() {
    asm volatile("cp.async.commit_group;" ::: "memory");
}
__device__ __forceinline__ void cp_wait0() {
    asm volatile("cp.async.wait_group 0;" ::: "memory");
}
__device__ __forceinline__ void ldsm_x4(uint32_t* r, uint32_t addr) {
    asm volatile("ldmatrix.sync.aligned.m8n8.x4.shared.b16 {%0,%1,%2,%3}, [%4];"
                 : "=r"(r[0]), "=r"(r[1]), "=r"(r[2]), "=r"(r[3]) : "r"(addr));
}
__device__ __forceinline__ void mma16816(float* c, const uint32_t* a,
                                         uint32_t b0, uint32_t b1) {
    asm volatile(
        "mma.sync.aligned.m16n8k16.row.col.f32.bf16.bf16.f32 "
        "{%0,%1,%2,%3}, {%4,%5,%6,%7}, {%8,%9}, {%0,%1,%2,%3};"
        : "+f"(c[0]), "+f"(c[1]), "+f"(c[2]), "+f"(c[3])
        : "r"(a[0]), "r"(a[1]), "r"(a[2]), "r"(a[3]), "r"(b0), "r"(b1));
}
// order-preserving float->u32 key; k in low bits => min = (min score, min k)
__device__ __forceinline__ u64 packsk(float s, int k) {
    uint32_t b = __float_as_uint(s);
    b = (b & 0x80000000u) ? ~b : (b | 0x80000000u);
    return ((u64)b << 32) | (uint32_t)k;
}
__device__ __forceinline__ float unpack_score(u64 v) {
    uint32_t b = (uint32_t)(v >> 32);
    b = (b & 0x80000000u) ? (b & 0x7fffffffu) : ~b;
    return __uint_as_float(b);
}

// ---------------------------------------------------------------------------
// Pre-pass: E fp32 -> bf16 row-major
// ---------------------------------------------------------------------------
__global__ void convE_kernel(const float* __restrict__ E) {
    int i = blockIdx.x * blockDim.x + threadIdx.x;          // float2 pairs
    const float2 v = reinterpret_cast<const float2*>(E)[i];
    __nv_bfloat162 b;
    b.x = __float2bfloat16_rn(v.x);
    b.y = __float2bfloat16_rn(v.y);
    reinterpret_cast<__nv_bfloat162*>(g_Ebf)[i] = b;
}

// ---------------------------------------------------------------------------
// Pre-pass: transpose-convert x[b][d][p] -> g_Zbf[n][d] bf16  (n = b*1024+p)
// ---------------------------------------------------------------------------
__global__ void convZ_kernel(const float* __restrict__ x) {
    __shared__ float t[32][129];
    const int bz = blockIdx.x;
    const int b  = bz >> 7;
    const int r  = bz & 127;
    const int dc = r >> 3;
    const int pc = r & 7;
    const int tid = threadIdx.x;

    const float* xb = x + (size_t)b * (D_ * P_) + (size_t)(dc * 32) * P_ + pc * 128;
#pragma unroll
    for (int j = 0; j < 16; j++) {
        int e = tid + j * 256;
        int d = e >> 7, p = e & 127;
        t[d][p] = xb[(size_t)d * P_ + p];
    }
    __syncthreads();

    const int n0 = b * P_ + pc * 128;
#pragma unroll
    for (int j = 0; j < 8; j++) {
        int f = tid + j * 256;
        int nl = f >> 4, d2 = f & 15;
        __nv_bfloat162 v;
        v.x = __float2bfloat16_rn(t[d2 * 2][nl]);
        v.y = __float2bfloat16_rn(t[d2 * 2 + 1][nl]);
        reinterpret_cast<__nv_bfloat162*>(g_Zbf)[(size_t)(n0 + nl) * (D_ / 2) + dc * 16 + d2] = v;
    }
}

// ---------------------------------------------------------------------------
// enorm[k] = sum_d E[k][d]^2  (exact fp32 on originals)
// ---------------------------------------------------------------------------
__global__ void enorm_kernel(const float* __restrict__ E) {
    int k    = blockIdx.x * 8 + (threadIdx.x >> 5);
    int lane = threadIdx.x & 31;
    const float* row = E + (size_t)k * D_;
    float s = 0.f;
#pragma unroll
    for (int d = lane; d < D_; d += 32) {
        float v = row[d];
        s = fmaf(v, v, s);
    }
#pragma unroll
    for (int o = 16; o; o >>= 1) s += __shfl_xor_sync(0xffffffffu, s, o);
    if (lane == 0) g_enorm[k] = s;
}

// ---------------------------------------------------------------------------
// Main: bf16 mma.sync GEMM + eps-window argmin + exact refinement + gather +
// transpose + loss.  512 threads = 16 warps: warp = (rowgrp 0..7, colgrp 0..1).
// Each warp: 16 rows x 16 cols per 32-code tile (1 A-ldsm + 1 B-ldsm + 2 MMA
// per k-step). Double-buffered B via cp.async.
// ---------------------------------------------------------------------------
__global__ __launch_bounds__(NTHR, 1)
void vq_main(const float* __restrict__ x, const float* __restrict__ E,
             float* __restrict__ out)
{
    extern __shared__ unsigned char sm_raw[];
    const uint32_t smem_base = smem_u32(sm_raw);
    float* en_sm  = reinterpret_cast<float*>(sm_raw + SM_EN);
    u64*   appmin = reinterpret_cast<u64*>(sm_raw + SM_APP);
    u64*   exmin  = reinterpret_cast<u64*>(sm_raw + SM_EX);
    int*   cntarr = reinterpret_cast<int*>(sm_raw + SM_CNT);
    int*   kbest  = reinterpret_cast<int*>(sm_raw + SM_KB);
    float* lred   = reinterpret_cast<float*>(sm_raw + SM_LRED);

    const int tid    = threadIdx.x;
    const int wid    = tid >> 5;
    const int lane   = tid & 31;
    const int rowgrp = wid & 7;
    const int colgrp = wid >> 3;
    const int n0     = blockIdx.x * TM;
    const int b      = n0 >> 10;
    const int p0     = n0 & (P_ - 1);
    const float* xb  = x + (size_t)b * (D_ * P_) + p0;   // xb[d*P_ + p]

    // exact enorm -> smem ; init reduction slots
#pragma unroll
    for (int j = 0; j < 8; j++) en_sm[tid + j * NTHR] = g_enorm[tid + j * NTHR];
    if (tid < TM) {
        appmin[tid] = ~0ull;
        exmin[tid]  = ~0ull;
        cntarr[tid] = 0;
    }

    // Stage A: 128 rows x 64 16B-chunks
#pragma unroll
    for (int i = 0; i < 16; i++) {
        int c = tid + i * NTHR;              // 0..8191
        int m = c >> 6, d8 = c & 63;
        cp_async16(smem_base + SM_A + (uint32_t)(m * ASTRIDE + d8 * 16),
                   g_Zbf + ((size_t)(n0 + m) * D_ + d8 * 8));
    }
    // Stage B tile 0: 32 rows x 64 chunks
#pragma unroll
    for (int i = 0; i < 4; i++) {
        int c = tid + i * NTHR;              // 0..2047
        int kk = c >> 6, d8 = c & 63;
        cp_async16(smem_base + SM_B0 + (uint32_t)(kk * ASTRIDE + d8 * 16),
                   g_Ebf + ((size_t)kk * D_ + d8 * 8));
    }
    cp_commit();
    cp_wait0();
    __syncthreads();

    // ldmatrix addressing
    const uint32_t aAddr = smem_base + SM_A
        + (uint32_t)((rowgrp * 16 + (lane & 15)) * ASTRIDE + (lane >> 4) * 16);
    const int bj   = lane >> 3;              // 0..3
    const int brow = ((bj >> 1) * 8) + (lane & 7);
    const int bkof = (bj & 1) * 16;
    const int tig  = lane & 3;

    // per-thread trackers: slot 0 -> row g, slot 1 -> row g+8 (g = lane>>2)
    float bestv[2] = {3.402823e38f, 3.402823e38f};
    int   besti[2] = {0, 0};
    float cv[2][4];
    int   ci[2][4];
#pragma unroll
    for (int s2 = 0; s2 < 2; s2++)
#pragma unroll
        for (int j = 0; j < 4; j++) { cv[s2][j] = 3.402823e38f; ci[s2][j] = 0; }

    for (int t = 0; t < NKT; ++t) {
        const int cur = t & 1;

        // prefetch next B tile (overlaps compute)
        if (t + 1 < NKT) {
            const int k0n = (t + 1) * TK;
#pragma unroll
            for (int i = 0; i < 4; i++) {
                int c = tid + i * NTHR;
                int kk = c >> 6, d8 = c & 63;
                cp_async16(smem_base + SM_B0 + (uint32_t)((cur ^ 1) * SM_BSZ
                                                          + kk * ASTRIDE + d8 * 16),
                           g_Ebf + ((size_t)(k0n + kk) * D_ + d8 * 8));
            }
        }
        cp_commit();

        // GEMM: this warp's 16 cols (colgrp*16 .. +15) = 2 n-tiles
        float acc[2][4];
#pragma unroll
        for (int n = 0; n < 2; n++)
#pragma unroll
            for (int j = 0; j < 4; j++) acc[n][j] = 0.f;

        const uint32_t bAddr = smem_base + SM_B0 + (uint32_t)(cur * SM_BSZ)
            + (uint32_t)((colgrp * 16 + brow) * ASTRIDE + bkof);

#pragma unroll 4
        for (int ks = 0; ks < 32; ks++) {
            uint32_t af[4], bf[4];
            ldsm_x4(af, aAddr + ks * 32);
            ldsm_x4(bf, bAddr + ks * 32);
            mma16816(acc[0], af, bf[0], bf[1]);
            mma16816(acc[1], af, bf[2], bf[3]);
        }

        // score + candidate tracking (approx scores, exact enorm)
        const int kt0 = t * TK + colgrp * 16;
#pragma unroll
        for (int n = 0; n < 2; n++) {
            const int kb = kt0 + n * 8 + tig * 2;
            const float2 en2 = *reinterpret_cast<const float2*>(&en_sm[kb]);
#pragma unroll
            for (int s2 = 0; s2 < 2; s2++) {
#pragma unroll
                for (int jj = 0; jj < 2; jj++) {
                    const int k = kb + jj;
                    float s = fmaf(-2.f, acc[n][s2 * 2 + jj],
                                   jj ? en2.y : en2.x);
                    if (s < bestv[s2] + EPS) {
                        int jm = 0; float vm = cv[s2][0];
#pragma unroll
                        for (int j = 1; j < 4; j++)
                            if (cv[s2][j] > vm) { vm = cv[s2][j]; jm = j; }
                        if (s < vm) { cv[s2][jm] = s; ci[s2][jm] = k; }
                        if (s < bestv[s2]) { bestv[s2] = s; besti[s2] = k; }
                    }
                }
            }
        }

        cp_wait0();
        __syncthreads();
    }

    // ---- finalize: smem packed-u64 argmin across the 8 threads per row ----
    const int rbase = rowgrp * 16 + (lane >> 2);     // row for s2=0; +8 for s2=1
#pragma unroll
    for (int s2 = 0; s2 < 2; s2++)
        atomicMin(&appmin[rbase + s2 * 8], packsk(bestv[s2], besti[s2]));
    __syncthreads();

#pragma unroll
    for (int s2 = 0; s2 < 2; s2++) {
        const int m = rbase + s2 * 8;
        const float gbv = unpack_score(appmin[m]);
        int c = 0;
#pragma unroll
        for (int j = 0; j < 4; j++)
            if (cv[s2][j] <= gbv + EPS) c++;
        if (c) atomicAdd(&cntarr[m], c);
    }
    __syncthreads();

#pragma unroll
    for (int s2 = 0; s2 < 2; s2++) {
        const int m = rbase + s2 * 8;
        if (cntarr[m] > 1) {
            const float gbv = unpack_score(appmin[m]);
#pragma unroll
            for (int j = 0; j < 4; j++) {
                if (cv[s2][j] <= gbv + EPS) {
                    const int kk2 = ci[s2][j];
                    const float* Er = E + (size_t)kk2 * D_;
                    float dot = 0.f;
#pragma unroll 8
                    for (int d = 0; d < D_; d++)
                        dot = fmaf(xb[(size_t)d * P_ + m], Er[d], dot);
                    float se = fmaf(-2.f, dot, en_sm[kk2]);
                    atomicMin(&exmin[m], packsk(se, kk2));
                }
            }
        }
    }
    __syncthreads();

    if (tid < TM)
        kbest[tid] = (cntarr[tid] > 1) ? (int)(exmin[tid] & 0xffffffffu)
                                       : (int)(appmin[tid] & 0xffffffffu);
    __syncthreads();

    // ---- gather + transpose write + loss (elementwise fp32 originals) ----
    const int p      = tid & 127;
    const int dstart = tid >> 7;            // 0..3
    const int myk    = kbest[p];
    const float* Er  = E + (size_t)myk * D_;
    float* ob        = out + (size_t)b * (D_ * P_) + p0;
    float lsum = 0.f;
#pragma unroll 4
    for (int d = dstart; d < D_; d += 4) {
        float q = Er[d];
        float z = xb[(size_t)d * P_ + p];
        ob[(size_t)d * P_ + p] = q;
        float df = z - q;
        lsum = fmaf(df, df, lsum);
    }

    __syncthreads();
    lred[tid] = lsum;
    __syncthreads();
    for (int s = NTHR / 2; s > 0; s >>= 1) {
        if (tid < s) lred[tid] += lred[tid + s];
        __syncthreads();
    }
    if (tid == 0) g_losspart[blockIdx.x] = lred[0];
}

// ---------------------------------------------------------------------------
// Final loss: loss = 1.25 * mean((z-q)^2)
// ---------------------------------------------------------------------------
__global__ void loss_kernel(float* __restrict__ out, int write_loss) {
    __shared__ float sh[NBLK];
    int tid = threadIdx.x;
    sh[tid] = g_losspart[tid];
    __syncthreads();
    for (int s = NBLK / 2; s > 0; s >>= 1) {
        if (tid < s) sh[tid] += sh[tid + s];
        __syncthreads();
    }
    if (tid == 0 && write_loss) {
        float m = sh[0] / (float)((size_t)N_ * D_);
        out[(size_t)N_ * D_] = m + 0.25f * m;
    }
}

extern "C" void kernel_launch(void* const* d_in, const int* in_sizes, int n_in,
                              void* d_out, int out_size) {
    const float* x = (const float*)d_in[0];
    const float* E = (const float*)d_in[1];
    if (n_in >= 2 && in_sizes[0] == K_ * D_ && in_sizes[1] == N_ * D_) {
        const float* t = x; x = E; E = t;   // defensive input-order swap
    }
    float* out = (float*)d_out;

    cudaFuncSetAttribute(vq_main, cudaFuncAttributeMaxDynamicSharedMemorySize, SM_TOTAL);

    convE_kernel<<<K_ * D_ / 2 / 256, 256>>>(E);
    convZ_kernel<<<4096, 256>>>(x);
    enorm_kernel<<<K_ / 8, 256>>>(E);
    vq_main<<<NBLK, NTHR, SM_TOTAL>>>(x, E, out);
    loss_kernel<<<1, NBLK>>>(out, out_size > N_ * D_ ? 1 : 0);
}